// round 5
// baseline (speedup 1.0000x reference)
#include <cuda_runtime.h>
#include <cuda_bf16.h>
#include <math.h>
#include <stdint.h>

#define N_TOKENS 131072
#define EMB_DIM  64
#define N_CODES  1024
#define DECAY_F       0.99f
#define OMD_F         ((float)(1.0 - 0.99))
#define EPS_F         1e-5f
#define COMMIT_HALF   0.125f
#define TPB           128

// ===================== device scratch =====================
__device__ int   g_idx[N_TOKENS];
__device__ float g_counts[N_CODES];
__device__ float g_dw[N_CODES * EMB_DIM];
__device__ float g_h[N_CODES];             // 0.5 * ||e_k||^2 (fp32)
__device__ float g_cs[N_CODES];
__device__ float g_embed_new[N_CODES * EMB_DIM];
__device__ float g_loss_accum;
// fragment-ordered bf16 codebook: [chunk(16)][slot(64)=(tile*4+ks)*2+plane][lane(32)] uint2
__device__ uint2 g_Bfrag[16 * 64 * 32];    // 256KB

// ===================== helpers =====================
__device__ __forceinline__ void split2(float x0, float x1, uint32_t& hi, uint32_t& lo) {
    __nv_bfloat16 h0 = __float2bfloat16(x0), h1 = __float2bfloat16(x1);
    __nv_bfloat16 l0 = __float2bfloat16(x0 - __bfloat162float(h0));
    __nv_bfloat16 l1 = __float2bfloat16(x1 - __bfloat162float(h1));
    hi = (uint32_t)__bfloat16_as_ushort(h0) | ((uint32_t)__bfloat16_as_ushort(h1) << 16);
    lo = (uint32_t)__bfloat16_as_ushort(l0) | ((uint32_t)__bfloat16_as_ushort(l1) << 16);
}

__device__ __forceinline__ void mma16816(float* c, const uint32_t* a, uint32_t b0, uint32_t b1) {
    asm volatile(
        "mma.sync.aligned.m16n8k16.row.col.f32.bf16.bf16.f32 "
        "{%0,%1,%2,%3},{%4,%5,%6,%7},{%8,%9},{%0,%1,%2,%3};"
        : "+f"(c[0]), "+f"(c[1]), "+f"(c[2]), "+f"(c[3])
        : "r"(a[0]), "r"(a[1]), "r"(a[2]), "r"(a[3]), "r"(b0), "r"(b1));
}

__device__ __forceinline__ void cp_async16(uint32_t dst_smem, const void* src) {
    asm volatile("cp.async.cg.shared.global [%0], [%1], 16;"
                 :: "r"(dst_smem), "l"(src) : "memory");
}
#define CP_COMMIT() asm volatile("cp.async.commit_group;" ::: "memory")
#define CP_WAIT(n)  asm volatile("cp.async.wait_group %0;" :: "n"(n) : "memory")

__device__ __forceinline__ uint32_t smem_u32(const void* p) {
    uint32_t a;
    asm("{ .reg .u64 t; cvta.to.shared.u64 t, %1; cvt.u32.u64 %0, t; }" : "=r"(a) : "l"(p));
    return a;
}

__device__ __forceinline__ void top2_ins(float v, int i, float& b1, int& i1, float& b2, int& i2) {
    if (v > b1 || (v == b1 && i < i1)) { b2 = b1; i2 = i1; b1 = v; i1 = i; }
    else if (v > b2 || (v == b2 && i < i2)) { b2 = v; i2 = i; }
}

// fp64 re-resolution: val = x.e - 0.5||e||^2 (x fp32 exact from smem)
__device__ double ddot_val(const float* __restrict__ x, const float* __restrict__ e) {
    double dot = 0.0, h = 0.0;
#pragma unroll
    for (int j = 0; j < EMB_DIM; j++) {
        double ev = (double)e[j];
        dot += (double)x[j] * ev;
        h   += ev * ev;
    }
    return dot - 0.5 * h;
}

// ===================== kernel 1: zero scratch =====================
__global__ void zero_scratch_kernel() {
    int i = blockIdx.x * blockDim.x + threadIdx.x;
    if (i < N_CODES) g_counts[i] = 0.0f;
    if (i < N_CODES * EMB_DIM) g_dw[i] = 0.0f;
    if (i == 0) g_loss_accum = 0.0f;
}

// ===================== kernel 2: prep (B fragments + h) =====================
__global__ void prep_kernel(const float* __restrict__ e) {
    int gid = blockIdx.x * blockDim.x + threadIdx.x;
    if (gid >= 128 * 32) return;
    int tn = gid >> 5, lane = gid & 31;
    int n = tn * 8 + (lane >> 2);
    int chunk = tn >> 3, tilein = tn & 7;
    const float* row = e + (size_t)n * EMB_DIM;
#pragma unroll
    for (int ks = 0; ks < 4; ks++) {
        int k = ks * 16 + (lane & 3) * 2;
        uint32_t h0, l0, h1, l1;
        split2(row[k], row[k + 1], h0, l0);
        split2(row[k + 8], row[k + 9], h1, l1);
        size_t base = ((size_t)chunk * 64 + (size_t)(tilein * 4 + ks) * 2) * 32 + lane;
        g_Bfrag[base]      = make_uint2(h0, h1);   // hi plane
        g_Bfrag[base + 32] = make_uint2(l0, l1);   // lo plane
    }
    if ((lane & 3) == 0) {
        float s = 0.0f;
#pragma unroll
        for (int j = 0; j < EMB_DIM; j++) s = fmaf(row[j], row[j], s);
        g_h[n] = 0.5f * s;
    }
}

// ===================== kernel 3: argmin via mma.sync + fused one-hot =====================
// smem: x_s 32KB | h_s 4KB | b0 16KB | b1 16KB | idx_s 512B
#define OFF_X    0
#define OFF_H    32768
#define OFF_B    36864      /* two 16KB buffers */
#define OFF_IDX  69632
#define SMEM_SZ  70144

__global__ __launch_bounds__(TPB)
void argmin_mma_kernel(const float* __restrict__ x_g,
                       const float* __restrict__ e_g,
                       float* __restrict__ enc_out) {
    extern __shared__ char smem[];
    float* x_s  = (float*)(smem + OFF_X);           // [128][64]
    float* h_s  = (float*)(smem + OFF_H);           // [1024]
    int*   idx_s = (int*)(smem + OFF_IDX);          // [128]
    uint32_t b_u32 = smem_u32(smem + OFF_B);

    int tid = threadIdx.x;
    int w = tid >> 5, lane = tid & 31;
    int g = lane >> 2, tg = lane & 3;
    int tb = blockIdx.x * TPB;

    // prefetch B chunk 0 via cp.async while doing x/h staging
    {
        const char* src = (const char*)&g_Bfrag[0];
#pragma unroll
        for (int it = 0; it < 8; it++)
            cp_async16(b_u32 + tid * 16 + it * (TPB * 16), src + tid * 16 + it * (TPB * 16));
        CP_COMMIT();
    }

    // stage 128 tokens (32KB) + h (4KB)
    {
        const uint4* src = (const uint4*)(x_g + (size_t)tb * EMB_DIM);
        uint4* dst = (uint4*)x_s;
#pragma unroll
        for (int i = 0; i < 16; i++) dst[tid + i * TPB] = src[tid + i * TPB];
        for (int i = tid; i < N_CODES; i += TPB) h_s[i] = g_h[i];
    }
    __syncthreads();

    // build A fragments (bf16 hi/lo) in registers
    uint32_t ahi[2][4][4], alo[2][4][4];
#pragma unroll
    for (int mt = 0; mt < 2; mt++) {
        int r0 = w * 32 + mt * 16 + g;
        int r1 = r0 + 8;
#pragma unroll
        for (int ks = 0; ks < 4; ks++) {
            int k = ks * 16 + tg * 2;
            split2(x_s[r0 * 64 + k],     x_s[r0 * 64 + k + 1], ahi[mt][ks][0], alo[mt][ks][0]);
            split2(x_s[r1 * 64 + k],     x_s[r1 * 64 + k + 1], ahi[mt][ks][1], alo[mt][ks][1]);
            split2(x_s[r0 * 64 + k + 8], x_s[r0 * 64 + k + 9], ahi[mt][ks][2], alo[mt][ks][2]);
            split2(x_s[r1 * 64 + k + 8], x_s[r1 * 64 + k + 9], ahi[mt][ks][3], alo[mt][ks][3]);
        }
    }

    float b1v[4], b2v[4]; int i1v[4], i2v[4];
#pragma unroll
    for (int t = 0; t < 4; t++) { b1v[t] = -3.4e38f; b2v[t] = -3.4e38f; i1v[t] = 0; i2v[t] = 0; }

    for (int c = 0; c < 16; c++) {
        // prefetch next chunk into the other buffer (that buffer was last read
        // in iteration c-1, which completed before last iteration's end-sync)
        if (c + 1 < 16) {
            const char* src = (const char*)&g_Bfrag[(size_t)(c + 1) * 2048];
            uint32_t dst = b_u32 + ((c + 1) & 1) * 16384;
#pragma unroll
            for (int it = 0; it < 8; it++)
                cp_async16(dst + tid * 16 + it * (TPB * 16), src + tid * 16 + it * (TPB * 16));
            CP_COMMIT();
            CP_WAIT(1);
        } else {
            CP_WAIT(0);
        }
        __syncthreads();

        const uint2* b_s = (const uint2*)(smem + OFF_B + (c & 1) * 16384);

        float cc[2][8][4];
#pragma unroll
        for (int mt = 0; mt < 2; mt++)
#pragma unroll
            for (int t = 0; t < 8; t++)
#pragma unroll
                for (int q = 0; q < 4; q++) cc[mt][t][q] = 0.0f;

#pragma unroll
        for (int tile = 0; tile < 8; tile++) {
#pragma unroll
            for (int ks = 0; ks < 4; ks++) {
                uint2 bh = b_s[((tile * 4 + ks) * 2 + 0) * 32 + lane];
                uint2 bl = b_s[((tile * 4 + ks) * 2 + 1) * 32 + lane];
#pragma unroll
                for (int mt = 0; mt < 2; mt++) {
                    mma16816(cc[mt][tile], ahi[mt][ks], bh.x, bh.y);
                    mma16816(cc[mt][tile], ahi[mt][ks], bl.x, bl.y);
                    mma16816(cc[mt][tile], alo[mt][ks], bh.x, bh.y);
                }
            }
        }

        // epilogue: val = dot - h ; top-2 update
#pragma unroll
        for (int mt = 0; mt < 2; mt++)
#pragma unroll
            for (int tile = 0; tile < 8; tile++) {
                int nb = c * 64 + tile * 8 + tg * 2;
                float2 hh = *(const float2*)&h_s[nb];
#pragma unroll
                for (int rh = 0; rh < 2; rh++) {
                    int tr = mt * 2 + rh;
                    top2_ins(cc[mt][tile][rh * 2 + 0] - hh.x, nb,     b1v[tr], i1v[tr], b2v[tr], i2v[tr]);
                    top2_ins(cc[mt][tile][rh * 2 + 1] - hh.y, nb + 1, b1v[tr], i1v[tr], b2v[tr], i2v[tr]);
                }
            }
        __syncthreads();
    }

    // merge top-2 across the quad
#pragma unroll
    for (int tr = 0; tr < 4; tr++) {
#pragma unroll
        for (int off = 1; off <= 2; off <<= 1) {
            float ov1 = __shfl_xor_sync(0xFFFFFFFFu, b1v[tr], off);
            int   oi1 = __shfl_xor_sync(0xFFFFFFFFu, i1v[tr], off);
            float ov2 = __shfl_xor_sync(0xFFFFFFFFu, b2v[tr], off);
            int   oi2 = __shfl_xor_sync(0xFFFFFFFFu, i2v[tr], off);
            top2_ins(ov1, oi1, b1v[tr], i1v[tr], b2v[tr], i2v[tr]);
            top2_ins(ov2, oi2, b1v[tr], i1v[tr], b2v[tr], i2v[tr]);
        }
    }

    // resolve + scatter (quad-parallel dw atomics)
#pragma unroll
    for (int tr = 0; tr < 4; tr++) {
        int lrow = w * 32 + (tr >> 1) * 16 + (tr & 1) * 8 + g;
        int idx = i1v[tr];
        if (tg == 0) {
            if (b1v[tr] - b2v[tr] < 1e-2f) {
                const float* xr = &x_s[lrow * 64];
                double v1 = ddot_val(xr, e_g + (size_t)idx * EMB_DIM);
                double v2 = ddot_val(xr, e_g + (size_t)i2v[tr] * EMB_DIM);
                if (v2 > v1 || (v2 == v1 && i2v[tr] < idx)) idx = i2v[tr];
            }
            idx_s[lrow] = idx;
            g_idx[tb + lrow] = idx;
            atomicAdd(&g_counts[idx], 1.0f);
        }
        idx = __shfl_sync(0xFFFFFFFFu, idx, lane & ~3);   // broadcast within quad
        float* dwrow = &g_dw[(size_t)idx * EMB_DIM + tg * 16];
        const float* xr = &x_s[lrow * 64 + tg * 16];
#pragma unroll
        for (int j = 0; j < 16; j++) atomicAdd(&dwrow[j], xr[j]);
    }
    __syncthreads();

    // fused one-hot write: branchless (NO dynamic-index local array), streaming stores
    {
        int colbase = tid * 8;
        const float ONE = 1.0f;
#pragma unroll 4
        for (int r = 0; r < TPB; r++) {
            int rel = idx_s[r] - colbase;
            uint2 v0 = make_uint2(rel == 0 ? __float_as_uint(ONE) : 0u,
                                  rel == 1 ? __float_as_uint(ONE) : 0u);
            uint2 v1 = make_uint2(rel == 2 ? __float_as_uint(ONE) : 0u,
                                  rel == 3 ? __float_as_uint(ONE) : 0u);
            uint2 v2 = make_uint2(rel == 4 ? __float_as_uint(ONE) : 0u,
                                  rel == 5 ? __float_as_uint(ONE) : 0u);
            uint2 v3 = make_uint2(rel == 6 ? __float_as_uint(ONE) : 0u,
                                  rel == 7 ? __float_as_uint(ONE) : 0u);
            uint2* dst = (uint2*)(enc_out + (size_t)(tb + r) * N_CODES + colbase);
            __stcs(dst + 0, v0);
            __stcs(dst + 1, v1);
            __stcs(dst + 2, v2);
            __stcs(dst + 3, v3);
        }
    }
}

// ===================== kernel 4: EMA stats + perplexity =====================
__global__ void stats_kernel(const float* __restrict__ ema_cs,
                             float* __restrict__ out_perp) {
    __shared__ float sh[N_CODES];
    int k = threadIdx.x;
    float cnt = g_counts[k];
    float cs = ema_cs[k] * DECAY_F + OMD_F * cnt;
    sh[k] = cs;
    __syncthreads();
    for (int s = N_CODES / 2; s > 0; s >>= 1) {
        if (k < s) sh[k] += sh[k + s];
        __syncthreads();
    }
    float n = sh[0];
    __syncthreads();
    float smooth = (cs + EPS_F) / (n + (float)N_CODES * EPS_F) * n;
    g_cs[k] = smooth;
    float p = cnt * (1.0f / (float)N_TOKENS);
    sh[k] = p * logf(p + 1e-10f);
    __syncthreads();
    for (int s = N_CODES / 2; s > 0; s >>= 1) {
        if (k < s) sh[k] += sh[k + s];
        __syncthreads();
    }
    if (k == 0) out_perp[0] = expf(-sh[0]);
}

// ===================== kernel 5: embedding_new =====================
__global__ void embed_new_kernel(const float* __restrict__ ema_w) {
    int i = blockIdx.x * blockDim.x + threadIdx.x;
    if (i >= N_CODES * EMB_DIM) return;
    int k = i >> 6;
    g_embed_new[i] = (ema_w[i] * DECAY_F + OMD_F * g_dw[i]) / g_cs[k];
}

// ===================== kernel 6: gather quantized + loss =====================
__global__ __launch_bounds__(TPB)
void quantize_kernel(const float* __restrict__ x_g,
                     float* __restrict__ q_out) {
    __shared__ float sred[TPB];
    int t = blockIdx.x * TPB + threadIdx.x;
    int idx = g_idx[t];
    const float4* xr = (const float4*)(x_g + (size_t)t * EMB_DIM);
    const float4* qr = (const float4*)(g_embed_new + (size_t)idx * EMB_DIM);
    float* outq = q_out + (size_t)t * EMB_DIM;   // 4B-aligned region: scalar stores
    float ss = 0.0f;
#pragma unroll
    for (int j = 0; j < 16; j++) {
        float4 xv = xr[j];
        float4 qv = qr[j];
        __stcs(&outq[4 * j + 0], qv.x); __stcs(&outq[4 * j + 1], qv.y);
        __stcs(&outq[4 * j + 2], qv.z); __stcs(&outq[4 * j + 3], qv.w);
        float dx = qv.x - xv.x, dy = qv.y - xv.y;
        float dz = qv.z - xv.z, dw = qv.w - xv.w;
        ss = fmaf(dx, dx, ss); ss = fmaf(dy, dy, ss);
        ss = fmaf(dz, dz, ss); ss = fmaf(dw, dw, ss);
    }
    sred[threadIdx.x] = ss;
    __syncthreads();
    for (int s = TPB / 2; s > 0; s >>= 1) {
        if (threadIdx.x < s) sred[threadIdx.x] += sred[threadIdx.x + s];
        __syncthreads();
    }
    if (threadIdx.x == 0) atomicAdd(&g_loss_accum, sred[0]);
}

// ===================== kernel 7: finalize loss =====================
__global__ void finalize_kernel(float* __restrict__ out_loss) {
    out_loss[0] = COMMIT_HALF * g_loss_accum / (float)N_TOKENS;
}

// ===================== launch =====================
extern "C" void kernel_launch(void* const* d_in, const int* in_sizes, int n_in,
                              void* d_out, int out_size) {
    const float* inputs  = (const float*)d_in[0];
    const float* embed_w = (const float*)d_in[1];
    const float* ema_w   = (const float*)d_in[2];
    const float* ema_cs  = (const float*)d_in[3];

    float* out = (float*)d_out;
    float* out_loss = out;
    float* out_q    = out + 1;
    float* out_perp = out + 1 + (size_t)N_TOKENS * EMB_DIM;
    float* out_enc  = out + 2 + (size_t)N_TOKENS * EMB_DIM;

    cudaFuncSetAttribute(argmin_mma_kernel,
                         cudaFuncAttributeMaxDynamicSharedMemorySize, SMEM_SZ);

    zero_scratch_kernel<<<(N_CODES * EMB_DIM + 255) / 256, 256>>>();
    prep_kernel<<<16, 256>>>(embed_w);
    argmin_mma_kernel<<<N_TOKENS / TPB, TPB, SMEM_SZ>>>(inputs, embed_w, out_enc);
    stats_kernel<<<1, N_CODES>>>(ema_cs, out_perp);
    embed_new_kernel<<<(N_CODES * EMB_DIM + 255) / 256, 256>>>(ema_w);
    quantize_kernel<<<N_TOKENS / TPB, TPB>>>(inputs, out_q);
    finalize_kernel<<<1, 1>>>(out_loss);
}